// round 15
// baseline (speedup 1.0000x reference)
#include <cuda_runtime.h>
#include <cuda_bf16.h>
#include <cstdint>

#define T_LEN 512
#define B_SZ  256
#define I_SZ  128
#define H_SZ  256
#define G_SZ  768
#define L_NUM 6

#define M_ROWS (T_LEN * B_SZ)                  // 131072
#define TBH    ((size_t)T_LEN * B_SZ * H_SZ)   // 33554432
#define BH     (B_SZ * H_SZ)                   // 65536

typedef unsigned long long ull;

// ------------------------------ scratch -----------------------------------
__device__ float g_gx[(size_t)M_ROWS * G_SZ];
__device__ float g_buf[2ULL * TBH];
__device__ __nv_bfloat16 g_ahi[(size_t)M_ROWS * 256];
__device__ __nv_bfloat16 g_alo[(size_t)M_ROWS * 256];
__device__ __nv_bfloat16 g_whi[G_SZ * 256];
__device__ __nv_bfloat16 g_wlo[G_SZ * 256];
__device__ __nv_bfloat16 g_hex[2][B_SZ][512];   // [parity][row][hi256|lo256]
__device__ __align__(128) ull g_bar2[16][16];

// ------------------------------ helpers -----------------------------------
__device__ __forceinline__ float tanh_f(float x) {
    float y; asm("tanh.approx.f32 %0, %1;" : "=f"(y) : "f"(x)); return y;
}
__device__ __forceinline__ float sigmf(float x) {
    return 0.5f * tanh_f(0.5f * x) + 0.5f;
}
__device__ __forceinline__ uint32_t smem_u32(const void* p) {
    uint32_t a;
    asm("{ .reg .u64 t; cvta.to.shared.u64 t, %1; cvt.u32.u64 %0, t; }"
        : "=r"(a) : "l"(p));
    return a;
}

// 8-CTA barrier per b-group (release arrive + acquire poll, monotonic ctr).
__device__ __forceinline__ void bg_barrier(int bg) {
    __syncthreads();
    if (threadIdx.x == 0) {
        ull* ctr = &g_bar2[bg][0];
        ull old;
        asm volatile("atom.release.gpu.global.add.u64 %0, [%1], 1;"
                     : "=l"(old) : "l"(ctr) : "memory");
        ull target = ((old + 1ULL + 7ULL) >> 3) << 3;
        if (old + 1ULL != target) {
            ull v;
            do {
                asm volatile("ld.acquire.gpu.global.u64 %0, [%1];"
                             : "=l"(v) : "l"(ctr) : "memory");
            } while (v < target);
        }
    }
    __syncthreads();
}

// ------------------------- fp32 -> bf16 hi/lo split -------------------------
__device__ __forceinline__ uint32_t bpack(float a, float b, bool lo) {
    __nv_bfloat16 ah = __float2bfloat16(a);
    __nv_bfloat16 bh = __float2bfloat16(b);
    if (lo) {
        ah = __float2bfloat16(a - __bfloat162float(ah));
        bh = __float2bfloat16(b - __bfloat162float(bh));
    }
    return (uint32_t)__bfloat16_as_ushort(ah) |
           ((uint32_t)__bfloat16_as_ushort(bh) << 16);
}

__global__ void conv_kernel(const float* __restrict__ A, const float* __restrict__ W,
                            int mk4, int wk4)
{
    int i = blockIdx.x * 256 + threadIdx.x;
    if (i < mk4) {
        float4 v = ((const float4*)A)[i];
        ((uint2*)g_ahi)[i] = make_uint2(bpack(v.x, v.y, false), bpack(v.z, v.w, false));
        ((uint2*)g_alo)[i] = make_uint2(bpack(v.x, v.y, true),  bpack(v.z, v.w, true));
    } else if (i < mk4 + wk4) {
        int j = i - mk4;
        float4 v = ((const float4*)W)[j];
        ((uint2*)g_whi)[j] = make_uint2(bpack(v.x, v.y, false), bpack(v.z, v.w, false));
        ((uint2*)g_wlo)[j] = make_uint2(bpack(v.x, v.y, true),  bpack(v.z, v.w, true));
    }
}

// ------------------------ mma primitives (proven) ---------------------------
__device__ __forceinline__ void ldmx4(uint32_t* r, uint32_t addr) {
    asm volatile("ldmatrix.sync.aligned.m8n8.x4.shared.b16 {%0,%1,%2,%3}, [%4];"
                 : "=r"(r[0]), "=r"(r[1]), "=r"(r[2]), "=r"(r[3]) : "r"(addr));
}
__device__ __forceinline__ void ldmx2(uint32_t* r, uint32_t addr) {
    asm volatile("ldmatrix.sync.aligned.m8n8.x2.shared.b16 {%0,%1}, [%2];"
                 : "=r"(r[0]), "=r"(r[1]) : "r"(addr));
}
__device__ __forceinline__ void mma16816(float* d, const uint32_t* a,
                                         uint32_t b0, uint32_t b1) {
    asm volatile(
        "mma.sync.aligned.m16n8k16.row.col.f32.bf16.bf16.f32 "
        "{%0,%1,%2,%3}, {%4,%5,%6,%7}, {%8,%9}, {%0,%1,%2,%3};"
        : "+f"(d[0]), "+f"(d[1]), "+f"(d[2]), "+f"(d[3])
        : "r"(a[0]), "r"(a[1]), "r"(a[2]), "r"(a[3]), "r"(b0), "r"(b1));
}
__device__ __forceinline__ void cpasync16(uint32_t saddr, const void* g) {
    asm volatile("cp.async.ca.shared.global [%0], [%1], 16;"
                 :: "r"(saddr), "l"(g) : "memory");
}

// ------------------------ mma.sync bf16 input GEMM (proven) ----------------
#define SR2  40
#define SR2B 80
#define T2   (128 * SR2B)               // 10240 B per tile
#define STAGE2 (4 * T2)                 // 40960 B per stage
#define GSM2 (2 * STAGE2)               // 81920 B

__global__ void __launch_bounds__(256, 2)
gemm_mma_kernel(const __nv_bfloat16* __restrict__ Ahi,
                const __nv_bfloat16* __restrict__ Alo,
                const __nv_bfloat16* __restrict__ Whi,
                const __nv_bfloat16* __restrict__ Wlo,
                const float* __restrict__ bias,
                float* __restrict__ C, int K)
{
    extern __shared__ char gsm[];
    const uint32_t sbase = smem_u32(gsm);

    const int tid = threadIdx.x;
    const int wid = tid >> 5;
    const int lane = tid & 31;
    const int wm = wid & 1;
    const int wn = wid >> 1;
    const int n0 = blockIdx.x * 128;
    const int m0 = blockIdx.y * 128;

    const int srow = tid >> 2;
    const int sq   = tid & 3;

    float acc[4][4][4];
    #pragma unroll
    for (int i = 0; i < 4; ++i)
        #pragma unroll
        for (int j = 0; j < 4; ++j)
            #pragma unroll
            for (int q = 0; q < 4; ++q) acc[i][j][q] = 0.0f;

    const int lrow = lane & 15;
    const int lkg  = (lane >> 4) * 8;
    const int nch = K >> 5;

    {
        #pragma unroll
        for (int p = 0; p < 2; ++p) {
            int row = srow + p * 64;
            uint32_t so = (uint32_t)(row * SR2B + sq * 16);
            size_t ga = (size_t)(m0 + row) * K + sq * 8;
            size_t gb = (size_t)(n0 + row) * K + sq * 8;
            cpasync16(sbase + so,          Ahi + ga);
            cpasync16(sbase + T2 + so,     Alo + ga);
            cpasync16(sbase + 2*T2 + so,   Whi + gb);
            cpasync16(sbase + 3*T2 + so,   Wlo + gb);
        }
        asm volatile("cp.async.commit_group;" ::: "memory");
    }

    for (int c = 0; c < nch; ++c) {
        if (c + 1 < nch) {
            uint32_t sb = sbase + ((c + 1) & 1) * STAGE2;
            #pragma unroll
            for (int p = 0; p < 2; ++p) {
                int row = srow + p * 64;
                uint32_t so = (uint32_t)(row * SR2B + sq * 16);
                size_t ga = (size_t)(m0 + row) * K + (c + 1) * 32 + sq * 8;
                size_t gb = (size_t)(n0 + row) * K + (c + 1) * 32 + sq * 8;
                cpasync16(sb + so,          Ahi + ga);
                cpasync16(sb + T2 + so,     Alo + ga);
                cpasync16(sb + 2*T2 + so,   Whi + gb);
                cpasync16(sb + 3*T2 + so,   Wlo + gb);
            }
            asm volatile("cp.async.commit_group;" ::: "memory");
            asm volatile("cp.async.wait_group 1;" ::: "memory");
        } else {
            asm volatile("cp.async.wait_group 0;" ::: "memory");
        }
        __syncthreads();

        const uint32_t st = sbase + (c & 1) * STAGE2;
        #pragma unroll
        for (int pass = 0; pass < 3; ++pass) {
            const uint32_t abase = st + (pass == 2 ? T2 : 0) +
                (uint32_t)((wm * 64 + lrow) * SR2B + lkg * 2);
            const uint32_t bbase = st + 2*T2 + (pass == 1 ? T2 : 0) +
                (uint32_t)((wn * 32 + lrow) * SR2B + lkg * 2);
            #pragma unroll
            for (int k16 = 0; k16 < 2; ++k16) {
                uint32_t a[4][4], b[2][4];
                #pragma unroll
                for (int mt = 0; mt < 4; ++mt)
                    ldmx4(a[mt], abase + mt * 16 * SR2B + k16 * 32);
                #pragma unroll
                for (int bh = 0; bh < 2; ++bh)
                    ldmx4(b[bh], bbase + bh * 16 * SR2B + k16 * 32);
                #pragma unroll
                for (int mt = 0; mt < 4; ++mt) {
                    #pragma unroll
                    for (int nt = 0; nt < 4; ++nt) {
                        int bh = nt >> 1, sub = nt & 1;
                        mma16816(acc[mt][nt], a[mt], b[bh][sub], b[bh][sub + 2]);
                    }
                }
            }
        }
        __syncthreads();
    }

    #pragma unroll
    for (int nt = 0; nt < 4; ++nt) {
        int col = n0 + wn * 32 + nt * 8 + (lane & 3) * 2;
        float2 bv = *(const float2*)(bias + col);
        #pragma unroll
        for (int mt = 0; mt < 4; ++mt) {
            int row = m0 + wm * 64 + mt * 16 + (lane >> 2);
            float2 o0 = { acc[mt][nt][0] + bv.x, acc[mt][nt][1] + bv.y };
            float2 o1 = { acc[mt][nt][2] + bv.x, acc[mt][nt][3] + bv.y };
            *(float2*)(C + (size_t)row * G_SZ + col) = o0;
            *(float2*)(C + (size_t)(row + 8) * G_SZ + col) = o1;
        }
    }
}

// ---------------------------------------------------------------------------
// Persistent recurrent scan on tensor cores, v4: 512 threads, k-split 4.
// 16 warps = 4 per SMSP; per warp 36 mma (chain 12), W frags 48 regs.
// W in registers, hp in registers, bf16 hi/lo exchange, A-split forwarding.
// ---------------------------------------------------------------------------
#define SROW  264
#define SROWB (SROW * 2)
#define WS_E  (96 * SROW)
#define AS_E  (16 * SROW)
#define SCAN_SMEM (2*WS_E*2 + 2*AS_E*2 + 3*128*12*4)   // 136704 B

__global__ void __launch_bounds__(512)
gru_scan_kernel(const float* __restrict__ Whh, const float* __restrict__ bhh,
                const float* __restrict__ gx, const float* __restrict__ hinit,
                float* __restrict__ out, float* __restrict__ finals, int wnext)
{
    extern __shared__ char sm[];
    __nv_bfloat16* WSH = (__nv_bfloat16*)sm;          // [96][264]
    __nv_bfloat16* WSL = WSH + WS_E;
    __nv_bfloat16* ASH = WSL + WS_E;                  // [16][264]
    __nv_bfloat16* ASL = ASH + AS_E;
    float* red = (float*)(ASL + AS_E);                // [3][128][12]

    const int tid = threadIdx.x;
    const int bg = blockIdx.x >> 3;      // 0..15
    const int hg = blockIdx.x & 7;       // 0..7
    const int b0 = bg * 16;
    const int h0 = hg * 32;

    // Split W_hh slice into smem bf16 hi/lo (used once to build fragments).
    for (int idx = tid; idx < 96 * 256; idx += 512) {
        int j = idx >> 8;
        int k = idx & 255;
        float v = Whh[(size_t)((j >> 5) * 256 + h0 + (j & 31)) * 256 + k];
        __nv_bfloat16 hb = __float2bfloat16(v);
        __nv_bfloat16 lb = __float2bfloat16(v - __bfloat162float(hb));
        WSH[j * SROW + k] = hb;
        WSL[j * SROW + k] = lb;
    }

    const int wid  = tid >> 5;           // 0..15
    const int L    = tid & 31;
    const int wmod = wid & 3;            // tile column group
    const int ks   = wid >> 2;           // 0..3 : k quarter
    const int kb16 = ks * 4;             // k16 base
    const int gr   = L >> 2;             // row 0..7 (and +8)
    const int ch   = h0 + wmod * 8 + (L & 3) * 2;
    const int tl   = tid & 127;          // (wmod, L) id within k-group

    float2 brv = *(const float2*)(bhh + ch);
    float2 bzv = *(const float2*)(bhh + 256 + ch);
    float2 bnv = *(const float2*)(bhh + 512 + ch);

    const uint32_t aH = smem_u32(ASH) +
        (uint32_t)((L & 15) * SROWB + (L >> 4) * 16);
    const uint32_t aL = aH + (uint32_t)(AS_E * 2);
    const uint32_t bHb = smem_u32(WSH) +
        (uint32_t)((L & 7) * SROWB + ((L >> 3) & 1) * 16);
    const uint32_t bLb = bHb + (uint32_t)(WS_E * 2);

    // stage h(t=0) from hinit (fp32 -> bf16 hi/lo tiles)
    {
        const float4* src4 = (const float4*)(hinit + (size_t)b0 * 256);
        #pragma unroll
        for (int p = 0; p < 2; ++p) {
            int f = tid + p * 512;
            int row = f >> 6;
            int kq = f & 63;
            float4 v = src4[row * 64 + kq];
            uint2 hiw, low;
            hiw.x = bpack(v.x, v.y, false); hiw.y = bpack(v.z, v.w, false);
            low.x = bpack(v.x, v.y, true);  low.y = bpack(v.z, v.w, true);
            *(uint2*)(ASH + row * SROW + kq * 4) = hiw;
            *(uint2*)(ASL + row * SROW + kq * 4) = low;
        }
    }

    // hp registers (finalizers) + gx prefetch for t=0
    float2 hp0, hp1, pr0, pz0, pn0, pr1, pz1, pn1;
    if (ks == 0) {
        hp0 = *(const float2*)(hinit + (size_t)(b0 + gr) * 256 + ch);
        hp1 = *(const float2*)(hinit + (size_t)(b0 + gr + 8) * 256 + ch);
        const float* q0 = gx + (size_t)(b0 + gr) * G_SZ + ch;
        const float* q1 = gx + (size_t)(b0 + gr + 8) * G_SZ + ch;
        pr0 = *(const float2*)(q0);       pr1 = *(const float2*)(q1);
        pz0 = *(const float2*)(q0 + 256); pz1 = *(const float2*)(q1 + 256);
        pn0 = *(const float2*)(q0 + 512); pn1 = *(const float2*)(q1 + 512);
    }

    __syncthreads();

    // Hoist W fragments into registers (this warp's k quarter only).
    uint32_t Bf0[3][4][2], Bf1[3][4][2];
    #pragma unroll
    for (int q = 0; q < 3; ++q) {
        const uint32_t nofs = (uint32_t)((wmod + q * 4) * 8 * SROWB);
        #pragma unroll
        for (int k16 = 0; k16 < 4; ++k16) {
            ldmx2(Bf0[q][k16], bHb + nofs + (kb16 + k16) * 32);
            ldmx2(Bf1[q][k16], bLb + nofs + (kb16 + k16) * 32);
        }
    }

    for (int t = 0; t < T_LEN; ++t) {
        if (t > 0) {
            // stage h(t-1): bf16 hi/lo straight copy from g_hex[t&1]
            const uint4* src = (const uint4*)(&g_hex[t & 1][b0][0]);
            #pragma unroll
            for (int p = 0; p < 2; ++p) {
                int f = tid + p * 512;            // 0..1023
                int row = f >> 6;
                int q = f & 63;
                uint4 v = __ldcv(src + row * 64 + q);
                __nv_bfloat16* dst = (q < 32)
                    ? (ASH + row * SROW + q * 8)
                    : (ASL + row * SROW + (q - 32) * 8);
                *(uint4*)dst = v;
            }
            __syncthreads();
        }

        float acc[3][4];
        #pragma unroll
        for (int q = 0; q < 3; ++q)
            #pragma unroll
            for (int i = 0; i < 4; ++i) acc[q][i] = 0.0f;

        #pragma unroll
        for (int pass = 0; pass < 3; ++pass) {
            uint32_t aB = (pass == 2) ? aL : aH;
            #pragma unroll
            for (int k16 = 0; k16 < 4; ++k16) {
                uint32_t a[4];
                ldmx4(a, aB + (kb16 + k16) * 32);
                #pragma unroll
                for (int q = 0; q < 3; ++q) {
                    if (pass == 1) mma16816(acc[q], a, Bf1[q][k16][0], Bf1[q][k16][1]);
                    else           mma16816(acc[q], a, Bf0[q][k16][0], Bf0[q][k16][1]);
                }
            }
        }

        if (ks > 0) {
            float* rp = red + ((ks - 1) * 128 + tl) * 12;
            #pragma unroll
            for (int q = 0; q < 3; ++q)
                #pragma unroll
                for (int i = 0; i < 4; ++i) rp[q * 4 + i] = acc[q][i];
        }
        __syncthreads();

        if (ks == 0) {
            #pragma unroll
            for (int s = 0; s < 3; ++s) {
                const float* rp = red + (s * 128 + tl) * 12;
                #pragma unroll
                for (int q = 0; q < 3; ++q)
                    #pragma unroll
                    for (int i = 0; i < 4; ++i) acc[q][i] += rp[q * 4 + i];
            }

            float rg0 = sigmf(pr0.x + acc[0][0] + brv.x);
            float rg1 = sigmf(pr0.y + acc[0][1] + brv.y);
            float zg0 = sigmf(pz0.x + acc[1][0] + bzv.x);
            float zg1 = sigmf(pz0.y + acc[1][1] + bzv.y);
            float ng0 = tanh_f(pn0.x + rg0 * (acc[2][0] + bnv.x));
            float ng1 = tanh_f(pn0.y + rg1 * (acc[2][1] + bnv.y));
            float2 hv0 = { (1.0f - zg0) * ng0 + zg0 * hp0.x,
                           (1.0f - zg1) * ng1 + zg1 * hp0.y };
            float rg2 = sigmf(pr1.x + acc[0][2] + brv.x);
            float rg3 = sigmf(pr1.y + acc[0][3] + brv.y);
            float zg2 = sigmf(pz1.x + acc[1][2] + bzv.x);
            float zg3 = sigmf(pz1.y + acc[1][3] + bzv.y);
            float ng2 = tanh_f(pn1.x + rg2 * (acc[2][2] + bnv.x));
            float ng3 = tanh_f(pn1.y + rg3 * (acc[2][3] + bnv.y));
            float2 hv1 = { (1.0f - zg2) * ng2 + zg2 * hp1.x,
                           (1.0f - zg3) * ng3 + zg3 * hp1.y };

            hp0 = hv0; hp1 = hv1;

            const size_t r0 = (size_t)t * B_SZ + b0 + gr;
            const size_t r1 = r0 + 8;
            *(float2*)(out + r0 * 256 + ch) = hv0;
            *(float2*)(out + r1 * 256 + ch) = hv1;

            uint32_t w0h = bpack(hv0.x, hv0.y, false);
            uint32_t w0l = bpack(hv0.x, hv0.y, true);
            uint32_t w1h = bpack(hv1.x, hv1.y, false);
            uint32_t w1l = bpack(hv1.x, hv1.y, true);

            if (wnext) {
                *(uint32_t*)(g_ahi + r0 * 256 + ch) = w0h;
                *(uint32_t*)(g_alo + r0 * 256 + ch) = w0l;
                *(uint32_t*)(g_ahi + r1 * 256 + ch) = w1h;
                *(uint32_t*)(g_alo + r1 * 256 + ch) = w1l;
            }

            if (t == T_LEN - 1) {
                *(float2*)(finals + (size_t)(b0 + gr) * 256 + ch) = hv0;
                *(float2*)(finals + (size_t)(b0 + gr + 8) * 256 + ch) = hv1;
            } else {
                int par = (t + 1) & 1;
                __nv_bfloat16* e0 = &g_hex[par][b0 + gr][0];
                __nv_bfloat16* e1 = &g_hex[par][b0 + gr + 8][0];
                *(uint32_t*)(e0 + ch)       = w0h;
                *(uint32_t*)(e0 + 256 + ch) = w0l;
                *(uint32_t*)(e1 + ch)       = w1h;
                *(uint32_t*)(e1 + 256 + ch) = w1l;

                const float* q0 = gx + ((size_t)(t + 1) * B_SZ + b0 + gr) * G_SZ + ch;
                const float* q1 = gx + ((size_t)(t + 1) * B_SZ + b0 + gr + 8) * G_SZ + ch;
                pr0 = *(const float2*)(q0);       pr1 = *(const float2*)(q1);
                pz0 = *(const float2*)(q0 + 256); pz1 = *(const float2*)(q1 + 256);
                pn0 = *(const float2*)(q0 + 512); pn1 = *(const float2*)(q1 + 512);
            }
        }

        if (t != T_LEN - 1) bg_barrier(bg);
    }
}

// ---------------------------------------------------------------------------
extern "C" void kernel_launch(void* const* d_in, const int* in_sizes, int n_in,
                              void* d_out, int out_size)
{
    const float* x     = (const float*)d_in[0];
    const float* h0    = (const float*)d_in[1];
    const float* Wih0  = (const float*)d_in[2];
    const float* Wih   = (const float*)d_in[3];
    const float* Whh   = (const float*)d_in[4];
    const float* bih   = (const float*)d_in[5];
    const float* bhh   = (const float*)d_in[6];
    float* out = (float*)d_out;

    float *gx_p = nullptr, *buf_p = nullptr;
    __nv_bfloat16 *ahi_p, *alo_p, *whi_p, *wlo_p;
    cudaGetSymbolAddress((void**)&gx_p,  g_gx);
    cudaGetSymbolAddress((void**)&buf_p, g_buf);
    cudaGetSymbolAddress((void**)&ahi_p, g_ahi);
    cudaGetSymbolAddress((void**)&alo_p, g_alo);
    cudaGetSymbolAddress((void**)&whi_p, g_whi);
    cudaGetSymbolAddress((void**)&wlo_p, g_wlo);

    cudaFuncSetAttribute(gru_scan_kernel,
                         cudaFuncAttributeMaxDynamicSharedMemorySize, SCAN_SMEM);
    cudaFuncSetAttribute(gemm_mma_kernel,
                         cudaFuncAttributeMaxDynamicSharedMemorySize, GSM2);

    for (int l = 0; l < L_NUM; ++l) {
        float*       lo  = (l == L_NUM - 1) ? out : buf_p + (size_t)(l & 1) * TBH;
        const int    K   = (l == 0) ? I_SZ : H_SZ;
        const float* Wi  = (l == 0) ? Wih0 : Wih + (size_t)(l - 1) * G_SZ * H_SZ;
        const float* Wh  = Whh + (size_t)l * G_SZ * H_SZ;
        const float* bi  = bih + (size_t)l * G_SZ;
        const float* bh  = bhh + (size_t)l * G_SZ;

        int mk4 = (l == 0) ? (M_ROWS * I_SZ / 4) : 0;
        int wk4 = G_SZ * K / 4;
        conv_kernel<<<(mk4 + wk4 + 255) / 256, 256>>>(x, Wi, mk4, wk4);

        dim3 gg(G_SZ / 128, M_ROWS / 128);
        gemm_mma_kernel<<<gg, 256, GSM2>>>(ahi_p, alo_p, whi_p, wlo_p,
                                           bi, gx_p, K);

        gru_scan_kernel<<<128, 512, SCAN_SMEM>>>(Wh, bh, gx_p,
                                                 h0 + (size_t)l * BH, lo,
                                                 out + TBH + (size_t)l * BH,
                                                 (l < L_NUM - 1) ? 1 : 0);
    }
}

// round 16
// speedup vs baseline: 1.0172x; 1.0172x over previous
#include <cuda_runtime.h>
#include <cuda_bf16.h>
#include <cstdint>

#define T_LEN 512
#define B_SZ  256
#define I_SZ  128
#define H_SZ  256
#define G_SZ  768
#define L_NUM 6

#define M_ROWS (T_LEN * B_SZ)                  // 131072
#define TBH    ((size_t)T_LEN * B_SZ * H_SZ)   // 33554432
#define BH     (B_SZ * H_SZ)                   // 65536

typedef unsigned long long ull;

// ------------------------------ scratch -----------------------------------
__device__ __nv_bfloat16 g_xhi[(size_t)M_ROWS * I_SZ];   // layer-0 input split
__device__ __nv_bfloat16 g_xlo[(size_t)M_ROWS * I_SZ];
__device__ __nv_bfloat16 g_ahi[(size_t)M_ROWS * H_SZ];   // inter-layer h split
__device__ __nv_bfloat16 g_alo[(size_t)M_ROWS * H_SZ];
__device__ __nv_bfloat16 g_hex[2][B_SZ][512];            // [parity][row][hi|lo]
__device__ __align__(128) ull g_bar2[16][16];

// ------------------------------ helpers -----------------------------------
__device__ __forceinline__ float tanh_f(float x) {
    float y; asm("tanh.approx.f32 %0, %1;" : "=f"(y) : "f"(x)); return y;
}
__device__ __forceinline__ float sigmf(float x) {
    return 0.5f * tanh_f(0.5f * x) + 0.5f;
}
__device__ __forceinline__ uint32_t smem_u32(const void* p) {
    uint32_t a;
    asm("{ .reg .u64 t; cvta.to.shared.u64 t, %1; cvt.u32.u64 %0, t; }"
        : "=r"(a) : "l"(p));
    return a;
}

// 8-CTA barrier per b-group (release arrive + acquire poll, monotonic ctr).
__device__ __forceinline__ void bg_barrier(int bg) {
    __syncthreads();
    if (threadIdx.x == 0) {
        ull* ctr = &g_bar2[bg][0];
        ull old;
        asm volatile("atom.release.gpu.global.add.u64 %0, [%1], 1;"
                     : "=l"(old) : "l"(ctr) : "memory");
        ull target = ((old + 1ULL + 7ULL) >> 3) << 3;
        if (old + 1ULL != target) {
            ull v;
            do {
                asm volatile("ld.acquire.gpu.global.u64 %0, [%1];"
                             : "=l"(v) : "l"(ctr) : "memory");
            } while (v < target);
        }
    }
    __syncthreads();
}

// ------------------------- fp32 -> bf16 hi/lo split -------------------------
__device__ __forceinline__ uint32_t bpack(float a, float b, bool lo) {
    __nv_bfloat16 ah = __float2bfloat16(a);
    __nv_bfloat16 bh = __float2bfloat16(b);
    if (lo) {
        ah = __float2bfloat16(a - __bfloat162float(ah));
        bh = __float2bfloat16(b - __bfloat162float(bh));
    }
    return (uint32_t)__bfloat16_as_ushort(ah) |
           ((uint32_t)__bfloat16_as_ushort(bh) << 16);
}

// split x (layer-0 input) into g_xhi/g_xlo
__global__ void conv_kernel(const float* __restrict__ A, int n4)
{
    int i = blockIdx.x * 256 + threadIdx.x;
    if (i < n4) {
        float4 v = ((const float4*)A)[i];
        ((uint2*)g_xhi)[i] = make_uint2(bpack(v.x, v.y, false), bpack(v.z, v.w, false));
        ((uint2*)g_xlo)[i] = make_uint2(bpack(v.x, v.y, true),  bpack(v.z, v.w, true));
    }
}

// ------------------------ mma primitives (proven) ---------------------------
__device__ __forceinline__ void ldmx4(uint32_t* r, uint32_t addr) {
    asm volatile("ldmatrix.sync.aligned.m8n8.x4.shared.b16 {%0,%1,%2,%3}, [%4];"
                 : "=r"(r[0]), "=r"(r[1]), "=r"(r[2]), "=r"(r[3]) : "r"(addr));
}
__device__ __forceinline__ void ldmx2(uint32_t* r, uint32_t addr) {
    asm volatile("ldmatrix.sync.aligned.m8n8.x2.shared.b16 {%0,%1}, [%2];"
                 : "=r"(r[0]), "=r"(r[1]) : "r"(addr));
}
__device__ __forceinline__ void mma16816(float* d, const uint32_t* a,
                                         uint32_t b0, uint32_t b1) {
    asm volatile(
        "mma.sync.aligned.m16n8k16.row.col.f32.bf16.bf16.f32 "
        "{%0,%1,%2,%3}, {%4,%5,%6,%7}, {%8,%9}, {%0,%1,%2,%3};"
        : "+f"(d[0]), "+f"(d[1]), "+f"(d[2]), "+f"(d[3])
        : "r"(a[0]), "r"(a[1]), "r"(a[2]), "r"(a[3]), "r"(b0), "r"(b1));
}
__device__ __forceinline__ void cpasync16(uint32_t saddr, const void* g) {
    asm volatile("cp.async.ca.shared.global [%0], [%1], 16;"
                 :: "r"(saddr), "l"(g) : "memory");
}

// ---------------------------------------------------------------------------
// Fully fused persistent GRU layer: per step computes BOTH the input
// projection (A_t x W_ih^T, mma from smem W) and the recurrent GEMM
// (h x W_hh^T, mma from register-hoisted W frags). 3-pass bf16 hi/lo
// everywhere; r/z accumulate ih+hh jointly, n kept split (GRU gating).
// 16 b-groups x 8 h-groups, 256 threads, k-split 2.
// ---------------------------------------------------------------------------
#define SROW  264
#define SROWB (SROW * 2)
#define AS_E  (16 * SROW)
#define WREG_B 101376                      // W region bytes (max of Whh/Wih)
#define SCAN_SMEM (WREG_B + 2*AS_E*2 + 2*(16*264)*2 + 8192)   // 143360

template<int KI>
__global__ void __launch_bounds__(256)
gru_scan_kernel(const float* __restrict__ Whh, const float* __restrict__ Wih,
                const float* __restrict__ bhh, const float* __restrict__ bih,
                const __nv_bfloat16* __restrict__ Ainh,
                const __nv_bfloat16* __restrict__ Ainl,
                const float* __restrict__ hinit,
                float* __restrict__ out, float* __restrict__ finals, int wnext)
{
    constexpr int SROWI = KI + 8;
    constexpr int WI_E  = 96 * SROWI;
    constexpr int AI_E  = 16 * SROWI;
    constexpr int KIH   = KI / 32;         // k16 steps per k-half
    constexpr int CH    = 16 * KI / 8;     // uint4 chunks per A tile

    extern __shared__ char sm[];
    __nv_bfloat16* Wsm = (__nv_bfloat16*)sm;              // Whh (prologue) then Wih
    __nv_bfloat16* ASH = (__nv_bfloat16*)(sm + WREG_B);   // h tile [16][264]
    __nv_bfloat16* ASL = ASH + AS_E;
    __nv_bfloat16* AIH = (__nv_bfloat16*)(sm + WREG_B + 2 * AS_E * 2);
    __nv_bfloat16* AIL = AIH + AI_E;
    float* red = (float*)(sm + WREG_B + 2 * AS_E * 2 + 2 * AI_E * 2);  // [128][16]

    const int tid = threadIdx.x;
    const int bg = blockIdx.x >> 3;      // 0..15
    const int hg = blockIdx.x & 7;       // 0..7
    const int b0 = bg * 16;
    const int h0 = hg * 32;

    const int wid  = tid >> 5;
    const int L    = tid & 31;
    const int wmod = wid & 3;
    const int ks   = wid >> 2;           // 0/1 : k-half
    const int gr   = L >> 2;             // row 0..7 (and +8)
    const int ch   = h0 + wmod * 8 + (L & 3) * 2;
    const int tl   = tid & 127;

    // ---- prologue phase 1: split W_hh into smem (SROW stride) ----
    {
        __nv_bfloat16* WhH = Wsm;
        __nv_bfloat16* WhL = Wsm + 96 * SROW;
        for (int idx = tid; idx < 96 * 256; idx += 256) {
            int j = idx >> 8;
            int k = idx & 255;
            float v = Whh[(size_t)((j >> 5) * 256 + h0 + (j & 31)) * 256 + k];
            __nv_bfloat16 hb = __float2bfloat16(v);
            WhH[j * SROW + k] = hb;
            WhL[j * SROW + k] = __float2bfloat16(v - __bfloat162float(hb));
        }
    }
    __syncthreads();

    // ---- hoist W_hh fragments to registers ----
    uint32_t Bf0[3][8][2], Bf1[3][8][2];
    {
        const uint32_t bHb = smem_u32(Wsm) +
            (uint32_t)((L & 7) * SROWB + ((L >> 3) & 1) * 16);
        const uint32_t bLb = bHb + (uint32_t)(96 * SROW * 2);
        #pragma unroll
        for (int q = 0; q < 3; ++q) {
            const uint32_t nofs = (uint32_t)((wmod + q * 4) * 8 * SROWB);
            #pragma unroll
            for (int kk = 0; kk < 8; ++kk) {
                ldmx2(Bf0[q][kk], bHb + nofs + (ks * 8 + kk) * 32);
                ldmx2(Bf1[q][kk], bLb + nofs + (ks * 8 + kk) * 32);
            }
        }
    }
    __syncthreads();

    // ---- prologue phase 2: split W_ih into the same smem (SROWI stride) ----
    for (int idx = tid; idx < 96 * KI; idx += 256) {
        int j = idx / KI;
        int k = idx % KI;
        float v = Wih[(size_t)((j >> 5) * 256 + h0 + (j & 31)) * KI + k];
        __nv_bfloat16 hb = __float2bfloat16(v);
        Wsm[j * SROWI + k] = hb;
        (Wsm + WI_E)[j * SROWI + k] = __float2bfloat16(v - __bfloat162float(hb));
    }

    // ---- stage A(0) and h(0) ----
    for (int f = tid; f < 2 * CH; f += 256) {
        int which = (f >= CH) ? 1 : 0;
        int g = f - which * CH;
        int row = g / (KI / 8);
        int q = g % (KI / 8);
        const __nv_bfloat16* src = (which ? Ainl : Ainh) +
            (size_t)(b0 + row) * KI + q * 8;
        __nv_bfloat16* dst = (which ? AIL : AIH) + row * SROWI + q * 8;
        *(uint4*)dst = *(const uint4*)src;
    }
    {
        const float4* src4 = (const float4*)(hinit + (size_t)b0 * 256);
        #pragma unroll
        for (int p = 0; p < 4; ++p) {
            int f = tid + p * 256;
            int row = f >> 6;
            int kq = f & 63;
            float4 v = src4[row * 64 + kq];
            uint2 hiw, low;
            hiw.x = bpack(v.x, v.y, false); hiw.y = bpack(v.z, v.w, false);
            low.x = bpack(v.x, v.y, true);  low.y = bpack(v.z, v.w, true);
            *(uint2*)(ASH + row * SROW + kq * 4) = hiw;
            *(uint2*)(ASL + row * SROW + kq * 4) = low;
        }
    }

    // biases + hp (finalizers)
    float2 br, bz, bni, bnh, hp0, hp1;
    if (ks == 0) {
        br.x  = bih[ch]       + bhh[ch];
        br.y  = bih[ch + 1]   + bhh[ch + 1];
        bz.x  = bih[256 + ch]     + bhh[256 + ch];
        bz.y  = bih[256 + ch + 1] + bhh[256 + ch + 1];
        bni   = *(const float2*)(bih + 512 + ch);
        bnh   = *(const float2*)(bhh + 512 + ch);
        hp0 = *(const float2*)(hinit + (size_t)(b0 + gr) * 256 + ch);
        hp1 = *(const float2*)(hinit + (size_t)(b0 + gr + 8) * 256 + ch);
    }

    __syncthreads();

    // ldmatrix bases (steady state)
    const uint32_t aH = smem_u32(ASH) +
        (uint32_t)((L & 15) * SROWB + (L >> 4) * 16);
    const uint32_t aL = aH + (uint32_t)(AS_E * 2);
    const uint32_t iH = smem_u32(AIH) +
        (uint32_t)((L & 15) * (SROWI * 2) + (L >> 4) * 16);
    const uint32_t iL = iH + (uint32_t)(AI_E * 2);
    const uint32_t wHb = smem_u32(Wsm) +
        (uint32_t)((L & 7) * (SROWI * 2) + ((L >> 3) & 1) * 16);
    const uint32_t wLb = wHb + (uint32_t)(WI_E * 2);
    const uint32_t aidst = smem_u32(AIH);

    for (int t = 0; t < T_LEN; ++t) {
        // stage h(t-1) from g_hex (barrier-ordered; t=0 staged in prologue)
        if (t > 0) {
            const uint4* src = (const uint4*)(&g_hex[t & 1][b0][0]);
            #pragma unroll
            for (int p = 0; p < 4; ++p) {
                int f = tid + p * 256;
                int row = f >> 6;
                int q = f & 63;
                uint4 v = __ldcv(src + row * 64 + q);
                __nv_bfloat16* dst = (q < 32)
                    ? (ASH + row * SROW + q * 8)
                    : (ASL + row * SROW + (q - 32) * 8);
                *(uint4*)dst = v;
            }
        }

        float aR[4] = {0,0,0,0}, aZ[4] = {0,0,0,0};
        float aNi[4] = {0,0,0,0}, aNh[4] = {0,0,0,0};

        // ---- ih GEMM: A_t x W_ih^T (W from smem, A from AIH/AIL) ----
        #pragma unroll
        for (int kk = 0; kk < KIH; ++kk) {
            const uint32_t kxo = (uint32_t)((ks * KIH + kk) * 32);
            uint32_t ah[4], al[4];
            ldmx4(ah, iH + kxo);
            ldmx4(al, iL + kxo);
            #pragma unroll
            for (int q = 0; q < 3; ++q) {
                uint32_t wh[2], wl[2];
                uint32_t no = (uint32_t)((wmod + q * 4) * 8 * (SROWI * 2)) + kxo;
                ldmx2(wh, wHb + no);
                ldmx2(wl, wLb + no);
                float* ac = (q == 0) ? aR : (q == 1) ? aZ : aNi;
                mma16816(ac, ah, wh[0], wh[1]);
                mma16816(ac, ah, wl[0], wl[1]);
                mma16816(ac, al, wh[0], wh[1]);
            }
        }
        __syncthreads();   // h tile visible; AIH/AIL free for prefetch

        // ---- hh GEMM: h x W_hh^T (W frags in registers) ----
        #pragma unroll
        for (int kk = 0; kk < 8; ++kk) {
            const uint32_t kxo = (uint32_t)((ks * 8 + kk) * 32);
            uint32_t ah[4], al[4];
            ldmx4(ah, aH + kxo);
            ldmx4(al, aL + kxo);
            #pragma unroll
            for (int q = 0; q < 3; ++q) {
                float* ac = (q == 0) ? aR : (q == 1) ? aZ : aNh;
                mma16816(ac, ah, Bf0[q][kk][0], Bf0[q][kk][1]);
                mma16816(ac, ah, Bf1[q][kk][0], Bf1[q][kk][1]);
                mma16816(ac, al, Bf0[q][kk][0], Bf0[q][kk][1]);
            }
        }

        // ---- prefetch A(t+1) via cp.async (waited before barrier) ----
        if (t + 1 < T_LEN) {
            for (int f = tid; f < 2 * CH; f += 256) {
                int which = (f >= CH) ? 1 : 0;
                int g = f - which * CH;
                int row = g / (KI / 8);
                int q = g % (KI / 8);
                const __nv_bfloat16* src = (which ? Ainl : Ainh) +
                    (size_t)((t + 1) * B_SZ + b0 + row) * KI + q * 8;
                uint32_t dst = aidst + (uint32_t)(which * AI_E * 2)
                             + (uint32_t)(row * (SROWI * 2) + q * 16);
                cpasync16(dst, src);
            }
            asm volatile("cp.async.commit_group;" ::: "memory");
        }

        // ---- k-half reduce ----
        if (ks == 1) {
            float* rp = red + tl * 16;
            #pragma unroll
            for (int i = 0; i < 4; ++i) {
                rp[i] = aR[i]; rp[4 + i] = aZ[i];
                rp[8 + i] = aNi[i]; rp[12 + i] = aNh[i];
            }
        }
        __syncthreads();

        if (ks == 0) {
            const float* rp = red + tl * 16;
            #pragma unroll
            for (int i = 0; i < 4; ++i) {
                aR[i] += rp[i]; aZ[i] += rp[4 + i];
                aNi[i] += rp[8 + i]; aNh[i] += rp[12 + i];
            }

            float rg0 = sigmf(aR[0] + br.x);
            float rg1 = sigmf(aR[1] + br.y);
            float zg0 = sigmf(aZ[0] + bz.x);
            float zg1 = sigmf(aZ[1] + bz.y);
            float ng0 = tanh_f(aNi[0] + bni.x + rg0 * (aNh[0] + bnh.x));
            float ng1 = tanh_f(aNi[1] + bni.y + rg1 * (aNh[1] + bnh.y));
            float2 hv0 = { (1.0f - zg0) * ng0 + zg0 * hp0.x,
                           (1.0f - zg1) * ng1 + zg1 * hp0.y };
            float rg2 = sigmf(aR[2] + br.x);
            float rg3 = sigmf(aR[3] + br.y);
            float zg2 = sigmf(aZ[2] + bz.x);
            float zg3 = sigmf(aZ[3] + bz.y);
            float ng2 = tanh_f(aNi[2] + bni.x + rg2 * (aNh[2] + bnh.x));
            float ng3 = tanh_f(aNi[3] + bni.y + rg3 * (aNh[3] + bnh.y));
            float2 hv1 = { (1.0f - zg2) * ng2 + zg2 * hp1.x,
                           (1.0f - zg3) * ng3 + zg3 * hp1.y };

            hp0 = hv0; hp1 = hv1;

            const size_t r0 = (size_t)t * B_SZ + b0 + gr;
            const size_t r1 = r0 + 8;

            uint32_t w0h = bpack(hv0.x, hv0.y, false);
            uint32_t w0l = bpack(hv0.x, hv0.y, true);
            uint32_t w1h = bpack(hv1.x, hv1.y, false);
            uint32_t w1l = bpack(hv1.x, hv1.y, true);

            if (wnext) {
                // next layer's input split (stride 256)
                *(uint32_t*)(g_ahi + r0 * 256 + ch) = w0h;
                *(uint32_t*)(g_alo + r0 * 256 + ch) = w0l;
                *(uint32_t*)(g_ahi + r1 * 256 + ch) = w1h;
                *(uint32_t*)(g_alo + r1 * 256 + ch) = w1l;
            } else {
                // last layer: fp32 sequence output
                *(float2*)(out + r0 * 256 + ch) = hv0;
                *(float2*)(out + r1 * 256 + ch) = hv1;
            }

            if (t == T_LEN - 1) {
                *(float2*)(finals + (size_t)(b0 + gr) * 256 + ch) = hv0;
                *(float2*)(finals + (size_t)(b0 + gr + 8) * 256 + ch) = hv1;
            } else {
                int par = (t + 1) & 1;
                __nv_bfloat16* e0 = &g_hex[par][b0 + gr][0];
                __nv_bfloat16* e1 = &g_hex[par][b0 + gr + 8][0];
                *(uint32_t*)(e0 + ch)       = w0h;
                *(uint32_t*)(e0 + 256 + ch) = w0l;
                *(uint32_t*)(e1 + ch)       = w1h;
                *(uint32_t*)(e1 + 256 + ch) = w1l;
            }
        }

        if (t + 1 < T_LEN) {
            asm volatile("cp.async.wait_group 0;" ::: "memory");
            bg_barrier(bg);   // also makes cp.async data CTA-visible
        }
    }
}

// ---------------------------------------------------------------------------
extern "C" void kernel_launch(void* const* d_in, const int* in_sizes, int n_in,
                              void* d_out, int out_size)
{
    const float* x     = (const float*)d_in[0];
    const float* h0    = (const float*)d_in[1];
    const float* Wih0  = (const float*)d_in[2];
    const float* Wih   = (const float*)d_in[3];
    const float* Whh   = (const float*)d_in[4];
    const float* bih   = (const float*)d_in[5];
    const float* bhh   = (const float*)d_in[6];
    float* out = (float*)d_out;

    __nv_bfloat16 *xhi_p, *xlo_p, *ahi_p, *alo_p;
    cudaGetSymbolAddress((void**)&xhi_p, g_xhi);
    cudaGetSymbolAddress((void**)&xlo_p, g_xlo);
    cudaGetSymbolAddress((void**)&ahi_p, g_ahi);
    cudaGetSymbolAddress((void**)&alo_p, g_alo);

    cudaFuncSetAttribute(gru_scan_kernel<128>,
                         cudaFuncAttributeMaxDynamicSharedMemorySize, SCAN_SMEM);
    cudaFuncSetAttribute(gru_scan_kernel<256>,
                         cudaFuncAttributeMaxDynamicSharedMemorySize, SCAN_SMEM);

    // split x once (layer-0 input)
    int n4 = M_ROWS * I_SZ / 4;
    conv_kernel<<<(n4 + 255) / 256, 256>>>(x, n4);

    for (int l = 0; l < L_NUM; ++l) {
        const float* Wi  = (l == 0) ? Wih0 : Wih + (size_t)(l - 1) * G_SZ * H_SZ;
        const float* Wh  = Whh + (size_t)l * G_SZ * H_SZ;
        const float* bi  = bih + (size_t)l * G_SZ;
        const float* bh  = bhh + (size_t)l * G_SZ;
        float* fin = out + TBH + (size_t)l * BH;
        int wnext = (l < L_NUM - 1) ? 1 : 0;

        if (l == 0) {
            gru_scan_kernel<128><<<128, 256, SCAN_SMEM>>>(
                Wh, Wi, bh, bi, xhi_p, xlo_p,
                h0 + (size_t)l * BH, out, fin, wnext);
        } else {
            gru_scan_kernel<256><<<128, 256, SCAN_SMEM>>>(
                Wh, Wi, bh, bi, ahi_p, alo_p,
                h0 + (size_t)l * BH, out, fin, wnext);
        }
    }
}